// round 1
// baseline (speedup 1.0000x reference)
#include <cuda_runtime.h>
#include <cuda_bf16.h>

// Problem constants: B=4, S=1024, D=1024, N=32, R=128 -> T = B*S = 4096 tokens.
// Stage 1: h[t,r]   = sum_{n,d} fw[t,n]*x[t,d]*FK[n,d,r]   (GEMM 4096 x 128  x 32768)
// Stage 2: out[t,d] = sum_{n,r} rw[t,n]*h[t,r]*RK[n,r,d]   (GEMM 4096 x 1024 x 4096)
// A is generated on the fly: A[t,k] = scaleW[t*32 + (k>>LOGD)] * src[t*SRCD + (k & (SRCD-1))]

#define T_TOKENS 4096
#define R_DIM 128
#define D_DIM 1024

// Scratch for h (4096 x 128 floats = 2 MB). Device global: allowed (no allocation).
__device__ float g_h[T_TOKENS * R_DIM];

__global__ void zero_kernel(float* __restrict__ p, int n) {
    int i = blockIdx.x * blockDim.x + threadIdx.x;
    if (i < n) p[i] = 0.0f;
}

// Tiled SGEMM with on-the-fly A construction.
// BM=BN=128, BK=8, 256 threads, 8x8 microtile per thread.
// NCOLS: width of B/C (ldb/ldc). SRCD: width of src rows (power of 2).
// LOGD: log2(SRCD) -> expert id = k >> LOGD. KCHUNK: K elements this CTA handles.
// ATOMIC: accumulate into C with atomicAdd (split-K) vs plain store.
template<int NCOLS, int SRCD, int LOGD, int KCHUNK, bool ATOMIC>
__global__ __launch_bounds__(256, 2)
void gemm_fly(const float* __restrict__ src,     // [T, SRCD]
              const float* __restrict__ sw,      // [T, 32] per-token expert weights
              const float* __restrict__ Bmat,    // [Ktotal, NCOLS] row-major
              float* __restrict__ Cmat)          // [T, NCOLS]
{
    constexpr int BM = 128, BN = 128, BK = 8;
    __shared__ float As[BK][BM];   // A stored transposed: As[k][m]
    __shared__ float Bs[BK][BN];

    const int tid = threadIdx.x;
    const int m0 = blockIdx.y * BM;
    const int n0 = blockIdx.x * BN;
    const int k0 = blockIdx.z * KCHUNK;

    // A loader: thread pair per row; each thread loads 4 consecutive k-elems (float4 from src)
    const int arow = tid >> 1;          // 0..127 (token row within tile)
    const int aq   = (tid & 1) * 4;     // k offset 0 or 4
    // B loader: 32 threads per k-row, float4 each
    const int brow = tid >> 5;          // 0..7
    const int bcol = (tid & 31) * 4;    // 0..124

    // Compute mapping: 16x16 thread grid, 8x8 outputs each
    const int tr = (tid >> 4) * 8;      // row offset in tile
    const int tc = (tid & 15) * 8;      // col offset in tile

    float acc[8][8];
#pragma unroll
    for (int i = 0; i < 8; i++)
#pragma unroll
        for (int j = 0; j < 8; j++) acc[i][j] = 0.0f;

    float areg[8], breg[8];

    const int at = m0 + arow;           // global token for A loader

    for (int kt = 0; kt < KCHUNK; kt += BK) {
        const int kg = k0 + kt;
        // ---- load A tile (on the fly, scaled by expert weight) ----
        {
            // BK=8 tiles are aligned, so the expert index is constant per tile
            const int ne = kg >> LOGD;
            const int d0 = (kg & (SRCD - 1)) + aq;
            const float s = sw[at * 32 + ne];
            const float4 xv = *reinterpret_cast<const float4*>(&src[(size_t)at * SRCD + d0]);
            As[aq + 0][arow] = s * xv.x;
            As[aq + 1][arow] = s * xv.y;
            As[aq + 2][arow] = s * xv.z;
            As[aq + 3][arow] = s * xv.w;
        }
        // ---- load B tile ----
        {
            const float4 bv = *reinterpret_cast<const float4*>(
                &Bmat[(size_t)(kg + brow) * NCOLS + n0 + bcol]);
            *reinterpret_cast<float4*>(&Bs[brow][bcol]) = bv;
        }
        __syncthreads();

        // ---- compute ----
#pragma unroll
        for (int kk = 0; kk < BK; kk++) {
            *reinterpret_cast<float4*>(&areg[0]) = *reinterpret_cast<const float4*>(&As[kk][tr]);
            *reinterpret_cast<float4*>(&areg[4]) = *reinterpret_cast<const float4*>(&As[kk][tr + 4]);
            *reinterpret_cast<float4*>(&breg[0]) = *reinterpret_cast<const float4*>(&Bs[kk][tc]);
            *reinterpret_cast<float4*>(&breg[4]) = *reinterpret_cast<const float4*>(&Bs[kk][tc + 4]);
#pragma unroll
            for (int i = 0; i < 8; i++)
#pragma unroll
                for (int j = 0; j < 8; j++)
                    acc[i][j] = fmaf(areg[i], breg[j], acc[i][j]);
        }
        __syncthreads();
    }

    // ---- epilogue ----
#pragma unroll
    for (int i = 0; i < 8; i++) {
        const size_t trow = (size_t)(m0 + tr + i) * NCOLS;
#pragma unroll
        for (int j = 0; j < 8; j++) {
            const int c = n0 + tc + j;
            if (ATOMIC) {
                atomicAdd(&Cmat[trow + c], acc[i][j]);
            } else {
                Cmat[trow + c] = acc[i][j];
            }
        }
    }
}

extern "C" void kernel_launch(void* const* d_in, const int* in_sizes, int n_in,
                              void* d_out, int out_size)
{
    const float* x  = (const float*)d_in[0];   // (4,1024,1024)
    const float* fw = (const float*)d_in[1];   // (4,1024,32)
    const float* rw = (const float*)d_in[2];   // (4,1024,32)
    const float* FK = (const float*)d_in[3];   // (32,1024,128) == B1 (32768,128)
    const float* RK = (const float*)d_in[4];   // (32,128,1024) == B2 (4096,1024)
    float* out = (float*)d_out;                // (4,1024,1024)

    float* hptr = nullptr;
    cudaGetSymbolAddress((void**)&hptr, g_h);

    // Zero h scratch (atomically accumulated each call; graph replays reuse it).
    {
        int n = T_TOKENS * R_DIM;  // 524288
        zero_kernel<<<(n + 255) / 256, 256>>>(hptr, n);
    }

    // Stage 1: h = sum_n (fw_n * x) @ FK[n]
    // GEMM M=4096, N=128, K=32768; split-K over 32 experts (chunks of 1024), atomic accumulate.
    {
        dim3 grid(R_DIM / 128, T_TOKENS / 128, 32);   // (1, 32, 32)
        gemm_fly<R_DIM, D_DIM, 10, 1024, true><<<grid, 256>>>(x, fw, FK, hptr);
    }

    // Stage 2: out = sum_n (rw_n * h) @ RK[n]
    // GEMM M=4096, N=1024, K=4096; full K per CTA, plain store (overwrites poison).
    {
        dim3 grid(D_DIM / 128, T_TOKENS / 128, 1);    // (8, 32, 1)
        gemm_fly<D_DIM, R_DIM, 7, 4096, false><<<grid, 256>>>(hptr, rw, RK, out);
    }
}

// round 2
// speedup vs baseline: 1.9540x; 1.9540x over previous
#include <cuda_runtime.h>
#include <cuda_bf16.h>
#include <cstdint>

// B=4, S=1024, D=1024, N=32, R=128 -> T = 4096 tokens.
// Stage 1: h[t,r]   = sum_{n,d} fw[t,n]*x[t,d]*FK[n,d,r]   (GEMM 4096 x 128  x 32768)
// Stage 2: out[t,d] = sum_{n,r} rw[t,n]*h[t,r]*RK[n,r,d]   (GEMM 4096 x 1024 x 4096)
// Tensor-core path: bf16 3-product split emulation of fp32 (a_hi*b_hi + a_hi*b_lo + a_lo*b_hi).

#define T_TOKENS 4096
#define R_DIM 128
#define D_DIM 1024

__device__ float g_h[T_TOKENS * R_DIM];   // 2 MB scratch for h

__global__ void zero_kernel(float4* __restrict__ p, int n4) {
    int i = blockIdx.x * blockDim.x + threadIdx.x;
    if (i < n4) p[i] = make_float4(0.f, 0.f, 0.f, 0.f);
}

__device__ __forceinline__ uint32_t smem_u32(const void* p) {
    return (uint32_t)__cvta_generic_to_shared(p);
}

__device__ __forceinline__ void ldsm_x4(uint32_t& r0, uint32_t& r1, uint32_t& r2, uint32_t& r3,
                                        uint32_t addr) {
    asm volatile("ldmatrix.sync.aligned.m8n8.x4.shared.b16 {%0,%1,%2,%3}, [%4];"
                 : "=r"(r0), "=r"(r1), "=r"(r2), "=r"(r3) : "r"(addr));
}
__device__ __forceinline__ void ldsm_x4_t(uint32_t& r0, uint32_t& r1, uint32_t& r2, uint32_t& r3,
                                          uint32_t addr) {
    asm volatile("ldmatrix.sync.aligned.m8n8.x4.trans.shared.b16 {%0,%1,%2,%3}, [%4];"
                 : "=r"(r0), "=r"(r1), "=r"(r2), "=r"(r3) : "r"(addr));
}
__device__ __forceinline__ void mma16816(float c[4], const uint32_t a[4],
                                         uint32_t b0, uint32_t b1) {
    asm volatile("mma.sync.aligned.m16n8k16.row.col.f32.bf16.bf16.f32 "
                 "{%0,%1,%2,%3},{%4,%5,%6,%7},{%8,%9},{%0,%1,%2,%3};"
                 : "+f"(c[0]), "+f"(c[1]), "+f"(c[2]), "+f"(c[3])
                 : "r"(a[0]), "r"(a[1]), "r"(a[2]), "r"(a[3]), "r"(b0), "r"(b1));
}

// Split fp32 into bf16 hi + bf16 lo (hi = RN(v), lo = RN(v - hi)).
__device__ __forceinline__ void split_bf16(float v, __nv_bfloat16& hi, __nv_bfloat16& lo) {
    hi = __float2bfloat16(v);
    lo = __float2bfloat16(v - __bfloat162float(hi));
}

// Tiled GEMM, A generated on the fly: A[t,k] = sw[t*32 + (k>>LOGD)] * src[t*SRCD + (k&(SRCD-1))]
// BM=128, BN=64, BK=32, 256 threads (8 warps, 4m x 2n grid of 32x32 warp tiles).
template<int NCOLS, int SRCD, int LOGD, int KCHUNK, bool ATOMIC>
__global__ __launch_bounds__(256, 2)
void gemm_bf16x3(const float* __restrict__ src,   // [T, SRCD]
                 const float* __restrict__ sw,    // [T, 32]
                 const float* __restrict__ Bmat,  // [Ktotal, NCOLS]
                 float* __restrict__ Cmat)        // [T, NCOLS]
{
    constexpr int BM = 128, BN = 64, BK = 32;
    constexpr int AP = BK + 8;   // A row pitch (bf16): 40 -> 80B, conflict-free ldsm strides
    constexpr int BP = BN + 8;   // B row pitch (bf16): 72 -> 144B

    __shared__ __nv_bfloat16 Ah[BM][AP], Al[BM][AP];
    __shared__ __nv_bfloat16 Bh[BK][BP], Bl[BK][BP];

    const int tid  = threadIdx.x;
    const int lane = tid & 31;
    const int wid  = tid >> 5;
    const int m0 = blockIdx.y * BM;
    const int n0 = blockIdx.x * BN;
    const int k0 = blockIdx.z * KCHUNK;
    const int wm = (wid >> 1) * 32;     // warp row offset in tile
    const int wn = (wid & 1) * 32;      // warp col offset in tile

    // Loader indices
    const int arow = tid >> 1;              // 0..127
    const int akof = (tid & 1) * 16;        // k offset 0/16
    const int brow = tid >> 3;              // 0..31
    const int bnof = (tid & 7) * 8;         // 0..56
    const int at   = m0 + arow;             // global token for A loader

    float acc[2][4][4];
#pragma unroll
    for (int mi = 0; mi < 2; mi++)
#pragma unroll
        for (int ni = 0; ni < 4; ni++)
#pragma unroll
            for (int q = 0; q < 4; q++) acc[mi][ni][q] = 0.f;

    const int lr = lane & 15;        // ldmatrix row-within-16
    const int lc = (lane >> 4) * 8;  // ldmatrix col half

    for (int kt = 0; kt < KCHUNK; kt += BK) {
        const int kg = k0 + kt;
        // ---- A tile: on-the-fly scale + split ----
        {
            const int ne = kg >> LOGD;                   // expert const per BK tile
            const float s = sw[at * 32 + ne];
            const float4* gp = reinterpret_cast<const float4*>(
                src + (size_t)at * SRCD + (kg & (SRCD - 1)) + akof);
#pragma unroll
            for (int i = 0; i < 4; i++) {
                float4 v = gp[i];
                v.x *= s; v.y *= s; v.z *= s; v.w *= s;
                __nv_bfloat16 hx, lx, hy, ly, hz, lz, hw, lw;
                split_bf16(v.x, hx, lx); split_bf16(v.y, hy, ly);
                split_bf16(v.z, hz, lz); split_bf16(v.w, hw, lw);
                *reinterpret_cast<__nv_bfloat162*>(&Ah[arow][akof + 4 * i])     = __halves2bfloat162(hx, hy);
                *reinterpret_cast<__nv_bfloat162*>(&Ah[arow][akof + 4 * i + 2]) = __halves2bfloat162(hz, hw);
                *reinterpret_cast<__nv_bfloat162*>(&Al[arow][akof + 4 * i])     = __halves2bfloat162(lx, ly);
                *reinterpret_cast<__nv_bfloat162*>(&Al[arow][akof + 4 * i + 2]) = __halves2bfloat162(lz, lw);
            }
        }
        // ---- B tile: split ----
        {
            const float4* gp = reinterpret_cast<const float4*>(
                Bmat + (size_t)(kg + brow) * NCOLS + n0 + bnof);
#pragma unroll
            for (int i = 0; i < 2; i++) {
                float4 v = gp[i];
                __nv_bfloat16 hx, lx, hy, ly, hz, lz, hw, lw;
                split_bf16(v.x, hx, lx); split_bf16(v.y, hy, ly);
                split_bf16(v.z, hz, lz); split_bf16(v.w, hw, lw);
                *reinterpret_cast<__nv_bfloat162*>(&Bh[brow][bnof + 4 * i])     = __halves2bfloat162(hx, hy);
                *reinterpret_cast<__nv_bfloat162*>(&Bh[brow][bnof + 4 * i + 2]) = __halves2bfloat162(hz, hw);
                *reinterpret_cast<__nv_bfloat162*>(&Bl[brow][bnof + 4 * i])     = __halves2bfloat162(lx, ly);
                *reinterpret_cast<__nv_bfloat162*>(&Bl[brow][bnof + 4 * i + 2]) = __halves2bfloat162(lz, lw);
            }
        }
        __syncthreads();

        // ---- compute: 2 k16 steps ----
#pragma unroll
        for (int ks = 0; ks < 2; ks++) {
            uint32_t ah[2][4], al_[2][4], bh[4][2], bl[4][2];
#pragma unroll
            for (int mi = 0; mi < 2; mi++) {
                ldsm_x4(ah[mi][0], ah[mi][1], ah[mi][2], ah[mi][3],
                        smem_u32(&Ah[wm + mi * 16 + lr][ks * 16 + lc]));
                ldsm_x4(al_[mi][0], al_[mi][1], al_[mi][2], al_[mi][3],
                        smem_u32(&Al[wm + mi * 16 + lr][ks * 16 + lc]));
            }
#pragma unroll
            for (int nb = 0; nb < 2; nb++) {
                ldsm_x4_t(bh[2 * nb][0], bh[2 * nb][1], bh[2 * nb + 1][0], bh[2 * nb + 1][1],
                          smem_u32(&Bh[ks * 16 + lr][wn + nb * 16 + lc]));
                ldsm_x4_t(bl[2 * nb][0], bl[2 * nb][1], bl[2 * nb + 1][0], bl[2 * nb + 1][1],
                          smem_u32(&Bl[ks * 16 + lr][wn + nb * 16 + lc]));
            }
#pragma unroll
            for (int mi = 0; mi < 2; mi++)
#pragma unroll
                for (int ni = 0; ni < 4; ni++) {
                    mma16816(acc[mi][ni], ah[mi],  bh[ni][0], bh[ni][1]);
                    mma16816(acc[mi][ni], ah[mi],  bl[ni][0], bl[ni][1]);
                    mma16816(acc[mi][ni], al_[mi], bh[ni][0], bh[ni][1]);
                }
        }
        __syncthreads();
    }

    // ---- epilogue ----
    const int grp = lane >> 2, tig = lane & 3;
#pragma unroll
    for (int mi = 0; mi < 2; mi++)
#pragma unroll
        for (int ni = 0; ni < 4; ni++) {
            const int row = m0 + wm + mi * 16 + grp;
            const int col = n0 + wn + ni * 8 + tig * 2;
            float* c0p = &Cmat[(size_t)row * NCOLS + col];
            float* c2p = &Cmat[(size_t)(row + 8) * NCOLS + col];
            if (ATOMIC) {
                atomicAdd(c0p,     acc[mi][ni][0]);
                atomicAdd(c0p + 1, acc[mi][ni][1]);
                atomicAdd(c2p,     acc[mi][ni][2]);
                atomicAdd(c2p + 1, acc[mi][ni][3]);
            } else {
                *reinterpret_cast<float2*>(c0p) = make_float2(acc[mi][ni][0], acc[mi][ni][1]);
                *reinterpret_cast<float2*>(c2p) = make_float2(acc[mi][ni][2], acc[mi][ni][3]);
            }
        }
}

extern "C" void kernel_launch(void* const* d_in, const int* in_sizes, int n_in,
                              void* d_out, int out_size)
{
    const float* x  = (const float*)d_in[0];   // (4,1024,1024)
    const float* fw = (const float*)d_in[1];   // (4,1024,32)
    const float* rw = (const float*)d_in[2];   // (4,1024,32)
    const float* FK = (const float*)d_in[3];   // (32,1024,128) == B1 (32768,128)
    const float* RK = (const float*)d_in[4];   // (32,128,1024) == B2 (4096,1024)
    float* out = (float*)d_out;                // (4,1024,1024)

    float* hptr = nullptr;
    cudaGetSymbolAddress((void**)&hptr, g_h);

    // Zero h (stage-1 accumulates atomically; graph replays reuse the buffer)
    {
        int n4 = (T_TOKENS * R_DIM) / 4;   // 131072
        zero_kernel<<<(n4 + 255) / 256, 256>>>((float4*)hptr, n4);
    }

    // Stage 1: M=4096, N=128, K=32768; split-K z=8 (KCHUNK=4096), atomic accumulate.
    {
        dim3 grid(R_DIM / 64, T_TOKENS / 128, 8);   // (2, 32, 8) = 512 CTAs
        gemm_bf16x3<R_DIM, D_DIM, 10, 4096, true><<<grid, 256>>>(x, fw, FK, hptr);
    }

    // Stage 2: M=4096, N=1024, K=4096; full K per CTA, plain store.
    {
        dim3 grid(D_DIM / 64, T_TOKENS / 128, 1);   // (16, 32) = 512 CTAs
        gemm_bf16x3<D_DIM, R_DIM, 7, 4096, false><<<grid, 256>>>(hptr, rw, RK, out);
    }
}

// round 4
// speedup vs baseline: 2.2624x; 1.1578x over previous
#include <cuda_runtime.h>
#include <cuda_bf16.h>
#include <cstdint>

// B=4,S=1024,D=1024,N=32,R=128 -> T=4096 tokens.
// Stage1: h[t,r]   = sum_n fw[t,n] * (x[t,:] . FK[n,:,r])     K=32768 (col of x = k&1023)
// Stage2: out[t,d] = sum_n rw[t,n] * (h[t,:] . RK[n,:,d])     K=4096  (col of h = k&127)
// bf16 3-product split (ah*bh + ah*bl + al*bh), fp32 accum, expert weights applied
// in-register at expert K-block boundaries (exact fp32 scaling).

#define TOK 4096

// ---- static device scratch ----
__device__ __nv_bfloat16 g_xh[TOK * 1024],  g_xl[TOK * 1024];    // x split
__device__ __nv_bfloat16 g_fkh[32768 * 128], g_fkl[32768 * 128]; // FK flat [k][r] split
__device__ __nv_bfloat16 g_rkh[4096 * 1024], g_rkl[4096 * 1024]; // RK flat [k][d] split
__device__ __nv_bfloat16 g_hh[TOK * 128],   g_hl[TOK * 128];     // h split
__device__ float         g_ph[8 * TOK * 128];                    // stage1 partial slabs

// ---- helpers ----
__device__ __forceinline__ uint32_t smem_u32(const void* p) {
    uint32_t a;
    asm("{ .reg .u64 t; cvta.to.shared.u64 t, %1; cvt.u32.u64 %0, t; }" : "=r"(a) : "l"(p));
    return a;
}
__device__ __forceinline__ void cp16(uint32_t dst, const void* src) {
    asm volatile("cp.async.cg.shared.global [%0], [%1], 16;" :: "r"(dst), "l"(src));
}
__device__ __forceinline__ void cp_commit() { asm volatile("cp.async.commit_group;" ::: "memory"); }
__device__ __forceinline__ void cp_wait1()  { asm volatile("cp.async.wait_group 1;" ::: "memory"); }

__device__ __forceinline__ void ldsm_x4(uint32_t* r, uint32_t addr) {
    asm volatile("ldmatrix.sync.aligned.m8n8.x4.shared.b16 {%0,%1,%2,%3}, [%4];"
                 : "=r"(r[0]), "=r"(r[1]), "=r"(r[2]), "=r"(r[3]) : "r"(addr));
}
__device__ __forceinline__ void ldsm_x4_t(uint32_t& r0, uint32_t& r1, uint32_t& r2, uint32_t& r3,
                                          uint32_t addr) {
    asm volatile("ldmatrix.sync.aligned.m8n8.x4.trans.shared.b16 {%0,%1,%2,%3}, [%4];"
                 : "=r"(r0), "=r"(r1), "=r"(r2), "=r"(r3) : "r"(addr));
}
__device__ __forceinline__ void mma16816(float c[4], const uint32_t a[4], uint32_t b0, uint32_t b1) {
    asm volatile("mma.sync.aligned.m16n8k16.row.col.f32.bf16.bf16.f32 "
                 "{%0,%1,%2,%3},{%4,%5,%6,%7},{%8,%9},{%0,%1,%2,%3};"
                 : "+f"(c[0]), "+f"(c[1]), "+f"(c[2]), "+f"(c[3])
                 : "r"(a[0]), "r"(a[1]), "r"(a[2]), "r"(a[3]), "r"(b0), "r"(b1));
}
__device__ __forceinline__ void split1(float v, __nv_bfloat16& h, __nv_bfloat16& l) {
    h = __float2bfloat16(v);
    l = __float2bfloat16(v - __bfloat162float(h));
}

// ---- prep: fp32 -> bf16 hi/lo (elementwise, vectorized) ----
__global__ void split_kernel(const float4* __restrict__ in, uint2* __restrict__ oh,
                             uint2* __restrict__ ol, int n4) {
    int i = blockIdx.x * blockDim.x + threadIdx.x;
    if (i >= n4) return;
    float4 v = in[i];
    __nv_bfloat16 hx, lx, hy, ly, hz, lz, hw, lw;
    split1(v.x, hx, lx); split1(v.y, hy, ly); split1(v.z, hz, lz); split1(v.w, hw, lw);
    __nv_bfloat162 h01 = __halves2bfloat162(hx, hy), h23 = __halves2bfloat162(hz, hw);
    __nv_bfloat162 l01 = __halves2bfloat162(lx, ly), l23 = __halves2bfloat162(lz, lw);
    uint2 uh, ul;
    uh.x = *reinterpret_cast<uint32_t*>(&h01); uh.y = *reinterpret_cast<uint32_t*>(&h23);
    ul.x = *reinterpret_cast<uint32_t*>(&l01); ul.y = *reinterpret_cast<uint32_t*>(&l23);
    oh[i] = uh; ol[i] = ul;
}

// ---- combine stage1 partial slabs -> h, split to bf16 ----
__global__ void combine_split_kernel(const float* __restrict__ ph,
                                     __nv_bfloat16* __restrict__ hh,
                                     __nv_bfloat16* __restrict__ hl) {
    int i = blockIdx.x * blockDim.x + threadIdx.x;  // < 4096*128
    float s = 0.f;
#pragma unroll
    for (int g = 0; g < 8; g++) s += ph[(size_t)g * (TOK * 128) + i];
    __nv_bfloat16 h, l; split1(s, h, l);
    hh[i] = h; hl[i] = l;
}

// ---- GEMM: BM=128, BN=64, BK=32, 256 thr, 3-stage cp.async, bf16x3 HMMA ----
// A logical [t][Ktot] with A[t,k] = src[t, k & AMASK]; weights applied at expert
// K-block (1<<LOGKE) boundaries: C += w[t,ne]*P.
// Output slab: Cout + blockIdx.z*TOK*NCOLS + row*NCOLS + col.
#define APITCH 80    // bytes per A smem row (32 bf16 + 8 pad)
#define BPITCH 144   // bytes per B smem row (64 bf16 + 8 pad)
#define OFF_AL 10240
#define OFF_BH 20480
#define OFF_BL 25088
#define SSTRIDE 29696
#define SMEM_TOTAL (3 * SSTRIDE)   // 89088

template<int NCOLS, int AW, int AMASK, int LOGKE, int TPE, int T>
__global__ __launch_bounds__(256, 2)
void gemm_ws(const __nv_bfloat16* __restrict__ ah_g, const __nv_bfloat16* __restrict__ al_g,
             const __nv_bfloat16* __restrict__ bh_g, const __nv_bfloat16* __restrict__ bl_g,
             const float* __restrict__ wg, float* __restrict__ Cout) {
    extern __shared__ char sm[];
    const uint32_t sb0 = smem_u32(sm);
    const int tid = threadIdx.x, lane = tid & 31, wid = tid >> 5;
    const int m0 = blockIdx.y * 128;
    const int n0 = blockIdx.x * 64;
    const int k0 = blockIdx.z * (T * 32);
    const int wm = (wid >> 1) * 32, wn = (wid & 1) * 32;

    // loader indices
    const int ar0 = (tid * 2) >> 2, ak0 = ((tid * 2) & 3) * 8;      // A chunk 0
    const int ar1 = (tid * 2 + 1) >> 2, ak1 = ((tid * 2 + 1) & 3) * 8;
    const int brow = tid >> 3, bn8 = (tid & 7) * 8;

    // ldmatrix indices
    const int lr = lane & 15, lc = (lane >> 4) * 8;
    const int grp = lane >> 2, tig = lane & 3;

    auto load_tile = [&](int t, int stg) {
        const int kg = k0 + t * 32;
        const uint32_t sb = sb0 + (uint32_t)stg * SSTRIDE;
        const int ac = kg & AMASK;
        cp16(sb + ar0 * APITCH + ak0 * 2,          ah_g + (size_t)(m0 + ar0) * AW + ac + ak0);
        cp16(sb + OFF_AL + ar0 * APITCH + ak0 * 2, al_g + (size_t)(m0 + ar0) * AW + ac + ak0);
        cp16(sb + ar1 * APITCH + ak1 * 2,          ah_g + (size_t)(m0 + ar1) * AW + ac + ak1);
        cp16(sb + OFF_AL + ar1 * APITCH + ak1 * 2, al_g + (size_t)(m0 + ar1) * AW + ac + ak1);
        const size_t bo = (size_t)(kg + brow) * NCOLS + n0 + bn8;
        cp16(sb + OFF_BH + brow * BPITCH + bn8 * 2, bh_g + bo);
        cp16(sb + OFF_BL + brow * BPITCH + bn8 * 2, bl_g + bo);
    };

    float P[2][4][4], C[2][4][4];
#pragma unroll
    for (int mi = 0; mi < 2; mi++)
#pragma unroll
        for (int ni = 0; ni < 4; ni++)
#pragma unroll
            for (int q = 0; q < 4; q++) { P[mi][ni][q] = 0.f; C[mi][ni][q] = 0.f; }

    load_tile(0, 0); cp_commit();
    load_tile(1, 1); cp_commit();

    for (int t = 0; t < T; t++) {
        cp_wait1();
        __syncthreads();
        if (t + 2 < T) load_tile(t + 2, (t + 2) % 3);
        cp_commit();

        const uint32_t sb = sb0 + (uint32_t)(t % 3) * SSTRIDE;
#pragma unroll
        for (int ks = 0; ks < 2; ks++) {
            uint32_t ah[2][4], al_[2][4], bh[4][2], bl[4][2];
#pragma unroll
            for (int mi = 0; mi < 2; mi++) {
                const uint32_t aaddr = sb + (uint32_t)(wm + mi * 16 + lr) * APITCH + (ks * 16 + lc) * 2;
                ldsm_x4(ah[mi], aaddr);
                ldsm_x4(al_[mi], aaddr + OFF_AL);
            }
#pragma unroll
            for (int nb = 0; nb < 2; nb++) {
                const uint32_t baddr = sb + OFF_BH + (uint32_t)(ks * 16 + lr) * BPITCH + (wn + nb * 16 + lc) * 2;
                ldsm_x4_t(bh[2 * nb][0], bh[2 * nb][1], bh[2 * nb + 1][0], bh[2 * nb + 1][1], baddr);
                ldsm_x4_t(bl[2 * nb][0], bl[2 * nb][1], bl[2 * nb + 1][0], bl[2 * nb + 1][1],
                          baddr + (OFF_BL - OFF_BH));
            }
#pragma unroll
            for (int mi = 0; mi < 2; mi++)
#pragma unroll
                for (int ni = 0; ni < 4; ni++) {
                    mma16816(P[mi][ni], ah[mi],  bh[ni][0], bh[ni][1]);
                    mma16816(P[mi][ni], ah[mi],  bl[ni][0], bl[ni][1]);
                    mma16816(P[mi][ni], al_[mi], bh[ni][0], bh[ni][1]);
                }
        }

        // expert boundary: fold weighted partial into C (exact fp32)
        if (((t + 1) & (TPE - 1)) == 0) {
            const int ne = (k0 + t * 32) >> LOGKE;
#pragma unroll
            for (int mi = 0; mi < 2; mi++) {
                const int rlo = m0 + wm + mi * 16 + grp;
                const float wlo = wg[rlo * 32 + ne];
                const float whi = wg[(rlo + 8) * 32 + ne];
#pragma unroll
                for (int ni = 0; ni < 4; ni++) {
                    C[mi][ni][0] += wlo * P[mi][ni][0];
                    C[mi][ni][1] += wlo * P[mi][ni][1];
                    C[mi][ni][2] += whi * P[mi][ni][2];
                    C[mi][ni][3] += whi * P[mi][ni][3];
                    P[mi][ni][0] = 0.f; P[mi][ni][1] = 0.f; P[mi][ni][2] = 0.f; P[mi][ni][3] = 0.f;
                }
            }
        }
    }

    // ---- epilogue ----
    float* ob = Cout + (size_t)blockIdx.z * TOK * NCOLS;
#pragma unroll
    for (int mi = 0; mi < 2; mi++)
#pragma unroll
        for (int ni = 0; ni < 4; ni++) {
            const int row = m0 + wm + mi * 16 + grp;
            const int col = n0 + wn + ni * 8 + tig * 2;
            *reinterpret_cast<float2*>(ob + (size_t)row * NCOLS + col) =
                make_float2(C[mi][ni][0], C[mi][ni][1]);
            *reinterpret_cast<float2*>(ob + (size_t)(row + 8) * NCOLS + col) =
                make_float2(C[mi][ni][2], C[mi][ni][3]);
        }
}

// ---- launch ----
extern "C" void kernel_launch(void* const* d_in, const int* in_sizes, int n_in,
                              void* d_out, int out_size) {
    const float* x  = (const float*)d_in[0];
    const float* fw = (const float*)d_in[1];
    const float* rw = (const float*)d_in[2];
    const float* FK = (const float*)d_in[3];   // (32,1024,128) = [32768][128]
    const float* RK = (const float*)d_in[4];   // (32,128,1024) = [4096][1024]
    float* out = (float*)d_out;

    __nv_bfloat16 *xh, *xl, *fkh, *fkl, *rkh, *rkl, *hh, *hl;
    float* ph;
    cudaGetSymbolAddress((void**)&xh, g_xh);   cudaGetSymbolAddress((void**)&xl, g_xl);
    cudaGetSymbolAddress((void**)&fkh, g_fkh); cudaGetSymbolAddress((void**)&fkl, g_fkl);
    cudaGetSymbolAddress((void**)&rkh, g_rkh); cudaGetSymbolAddress((void**)&rkl, g_rkl);
    cudaGetSymbolAddress((void**)&hh, g_hh);   cudaGetSymbolAddress((void**)&hl, g_hl);
    cudaGetSymbolAddress((void**)&ph, g_ph);

    cudaFuncSetAttribute(gemm_ws<128, 1024, 1023, 10, 32, 128>,
                         cudaFuncAttributeMaxDynamicSharedMemorySize, SMEM_TOTAL);
    cudaFuncSetAttribute(gemm_ws<1024, 128, 127, 7, 4, 128>,
                         cudaFuncAttributeMaxDynamicSharedMemorySize, SMEM_TOTAL);

    // 1-3: split all fp32 operands to bf16 hi/lo (each 4.19M elems = 1.05M float4)
    split_kernel<<<4096, 256>>>((const float4*)x,  (uint2*)xh,  (uint2*)xl,  1048576);
    split_kernel<<<4096, 256>>>((const float4*)FK, (uint2*)fkh, (uint2*)fkl, 1048576);
    split_kernel<<<4096, 256>>>((const float4*)RK, (uint2*)rkh, (uint2*)rkl, 1048576);

    // 4: stage-1 GEMM, split-K z=8 (4 experts/chunk), fw folded at boundaries -> 8 slabs
    gemm_ws<128, 1024, 1023, 10, 32, 128>
        <<<dim3(2, 32, 8), 256, SMEM_TOTAL>>>(xh, xl, fkh, fkl, fw, ph);

    // 5: combine slabs -> h, split to bf16
    combine_split_kernel<<<(TOK * 128) / 256, 256>>>(ph, hh, hl);

    // 6: stage-2 GEMM, rw folded at boundaries -> out   (launch idx 5: profiled by -s 5)
    gemm_ws<1024, 128, 127, 7, 4, 128>
        <<<dim3(16, 32, 1), 256, SMEM_TOTAL>>>(hh, hl, rkh, rkl, rw, out);
}